// round 9
// baseline (speedup 1.0000x reference)
#include <cuda_runtime.h>
#include <cuda_bf16.h>
#include <cstdint>
#include <math.h>

#define RTOT 4096       // b*s
#define DM   1024
#define NS   16
#define PP   96
#define SSEQ 2048

// ---------------- scratch (device globals; no allocs allowed) ----------------
__device__ float g_xin [RTOT*DM];   // x @ w_in           (r, d)
__device__ float g_proj[RTOT*PP];   // x_in @ w_x         (r, 96)
__device__ float g_dt  [RTOT*DM];   // dt after softplus  (r, d)
__device__ float g_dtT [RTOT*DM];   // dt transposed      (b, d, t)
__device__ float g_uT  [RTOT*DM];   // x_in transposed    (b, d, t)
__device__ float g_inp [RTOT*NS];   // B * (s @ Aneg)     (r, n)
__device__ float g_Cbuf[RTOT*NS];   // packed C           (r, n)
__device__ float g_Aneg[DM*NS];     // -exp(A_log)
// bf16 split operands for tensor-core GEMM1
__device__ __nv_bfloat16 g_xh [RTOT*DM];   // hi(x)
__device__ __nv_bfloat16 g_xl [RTOT*DM];   // lo(x)
__device__ __nv_bfloat16 g_whT[DM*DM];     // hi(w_in)^T  [n][k]
__device__ __nv_bfloat16 g_wlT[DM*DM];     // lo(w_in)^T  [n][k]

// ---------------- A = -exp(A_log) ----------------
__global__ void aneg_kernel(const float* __restrict__ A_log) {
    int i = blockIdx.x * blockDim.x + threadIdx.x;
    if (i < DM * NS) g_Aneg[i] = -expf(A_log[i]);
}

// ---------------- convert x -> bf16 hi/lo (vectorized) ----------------
__global__ void convert_x_kernel(const float* __restrict__ x) {
    int i = blockIdx.x * 256 + threadIdx.x;       // handles 4 floats
    float4 v = ((const float4*)x)[i];
    __nv_bfloat16 h0 = __float2bfloat16(v.x);
    __nv_bfloat16 h1 = __float2bfloat16(v.y);
    __nv_bfloat16 h2 = __float2bfloat16(v.z);
    __nv_bfloat16 h3 = __float2bfloat16(v.w);
    __nv_bfloat16 l0 = __float2bfloat16(v.x - __bfloat162float(h0));
    __nv_bfloat16 l1 = __float2bfloat16(v.y - __bfloat162float(h1));
    __nv_bfloat16 l2 = __float2bfloat16(v.z - __bfloat162float(h2));
    __nv_bfloat16 l3 = __float2bfloat16(v.w - __bfloat162float(h3));
    __nv_bfloat162 ph0; ph0.x = h0; ph0.y = h1;
    __nv_bfloat162 ph1; ph1.x = h2; ph1.y = h3;
    __nv_bfloat162 pl0; pl0.x = l0; pl0.y = l1;
    __nv_bfloat162 pl1; pl1.x = l2; pl1.y = l3;
    __nv_bfloat162* ph = (__nv_bfloat162*)g_xh;
    __nv_bfloat162* pl = (__nv_bfloat162*)g_xl;
    ph[i * 2]     = ph0;
    ph[i * 2 + 1] = ph1;
    pl[i * 2]     = pl0;
    pl[i * 2 + 1] = pl1;
}

// ---------------- convert w_in -> transposed bf16 hi/lo ----------------
// w[k][n] (1024x1024) -> whT[n][k], wlT[n][k]
__global__ void convert_w_kernel(const float* __restrict__ w) {
    __shared__ float t[32][33];
    int kbase = blockIdx.y * 32, nbase = blockIdx.x * 32;
#pragma unroll
    for (int j = threadIdx.y; j < 32; j += 8)
        t[j][threadIdx.x] = w[(kbase + j) * DM + nbase + threadIdx.x];
    __syncthreads();
#pragma unroll
    for (int j = threadIdx.y; j < 32; j += 8) {
        float v = t[threadIdx.x][j];               // = w[kbase+tx][nbase+j]
        __nv_bfloat16 h = __float2bfloat16(v);
        __nv_bfloat16 l = __float2bfloat16(v - __bfloat162float(h));
        g_whT[(nbase + j) * DM + kbase + threadIdx.x] = h;
        g_wlT[(nbase + j) * DM + kbase + threadIdx.x] = l;
    }
}

// ---------------- tensor-core GEMM1 helpers ----------------
__device__ __forceinline__ void ldsm4(uint32_t& r0, uint32_t& r1, uint32_t& r2, uint32_t& r3,
                                      uint32_t addr) {
    asm volatile("ldmatrix.sync.aligned.m8n8.x4.shared.b16 {%0,%1,%2,%3},[%4];"
                 : "=r"(r0), "=r"(r1), "=r"(r2), "=r"(r3) : "r"(addr));
}
__device__ __forceinline__ void mma16816(float* c, const uint32_t* a, uint32_t b0, uint32_t b1) {
    asm volatile(
        "mma.sync.aligned.m16n8k16.row.col.f32.bf16.bf16.f32 "
        "{%0,%1,%2,%3},{%4,%5,%6,%7},{%8,%9},{%0,%1,%2,%3};"
        : "+f"(c[0]), "+f"(c[1]), "+f"(c[2]), "+f"(c[3])
        : "r"(a[0]), "r"(a[1]), "r"(a[2]), "r"(a[3]), "r"(b0), "r"(b1));
}
__device__ __forceinline__ void cp16(uint32_t saddr, const void* g) {
    asm volatile("cp.async.cg.shared.global [%0],[%1],16;" ::"r"(saddr), "l"(g) : "memory");
}
__device__ __forceinline__ void cp_commit() {
    asm volatile("cp.async.commit_group;" ::: "memory");
}

// issue async loads of one BK=32 stage (4 tiles of [128][40] bf16, 10240B each)
__device__ __forceinline__ void issue_stage(uint32_t smem_u32, int tid,
                                            const __nv_bfloat16* s0, const __nv_bfloat16* s1,
                                            const __nv_bfloat16* s2, const __nv_bfloat16* s3,
                                            int stage, int k0) {
    uint32_t sbase = smem_u32 + stage * 40960;
    const __nv_bfloat16* srcs[4];
    srcs[0] = s0; srcs[1] = s1; srcs[2] = s2; srcs[3] = s3;
#pragma unroll
    for (int tile = 0; tile < 4; tile++) {
        const __nv_bfloat16* src = srcs[tile];
        uint32_t toff = sbase + tile * 10240;
#pragma unroll
        for (int i = 0; i < 2; i++) {
            int c = tid + i * 256;
            int row = c >> 2, q = c & 3;
            cp16(toff + row * 80 + q * 16, src + row * DM + k0 + q * 8);
        }
    }
    cp_commit();
}

// smem per stage: tiles 0=Ah 1=Al 2=Bh 3=Bl; stage stride 40960B; total 81920B
// epilogue reuses smem as float[128][129] transpose stage (66048B <= 81920B)
__global__ __launch_bounds__(256) void mma_gemm_kernel() {
    extern __shared__ __align__(16) char smem_raw[];
    uint32_t smem_u32 = (uint32_t)__cvta_generic_to_shared(smem_raw);

    int tid = threadIdx.x;
    int wid = tid >> 5, lane = tid & 31;
    int warpM = wid & 3, warpN = wid >> 2;
    int m0 = blockIdx.y * 128;
    int n0 = blockIdx.x * 128;

    const __nv_bfloat16* sxh = g_xh + (size_t)m0 * DM;
    const __nv_bfloat16* sxl = g_xl + (size_t)m0 * DM;
    const __nv_bfloat16* swh = g_whT + (size_t)n0 * DM;
    const __nv_bfloat16* swl = g_wlT + (size_t)n0 * DM;

    float acc[2][8][4];
#pragma unroll
    for (int mt = 0; mt < 2; mt++)
#pragma unroll
        for (int nt = 0; nt < 8; nt++)
#pragma unroll
            for (int e = 0; e < 4; e++) acc[mt][nt][e] = 0.f;

    // ldmatrix per-lane address components
    int a_row = lane & 15;
    int a_k   = (lane >> 4) << 3;
    int b_row = (lane & 7) + ((lane >> 4) << 3);
    int b_k   = ((lane >> 3) & 1) << 3;

    issue_stage(smem_u32, tid, sxh, sxl, swh, swl, 0, 0);

    const int NK = 32;  // 1024 / 32
    for (int kt = 0; kt < NK; kt++) {
        if (kt + 1 < NK) {
            issue_stage(smem_u32, tid, sxh, sxl, swh, swl, (kt + 1) & 1, (kt + 1) * 32);
            asm volatile("cp.async.wait_group 1;" ::: "memory");
        } else {
            asm volatile("cp.async.wait_group 0;" ::: "memory");
        }
        __syncthreads();

        uint32_t sbase = smem_u32 + (kt & 1) * 40960;
#pragma unroll
        for (int ks = 0; ks < 2; ks++) {
            int kk = ks * 16;
            uint32_t ah[2][4], al[2][4];
#pragma unroll
            for (int mt = 0; mt < 2; mt++) {
                int mrow = warpM * 32 + mt * 16 + a_row;
                uint32_t ad = sbase + (mrow * 40 + kk + a_k) * 2;
                ldsm4(ah[mt][0], ah[mt][1], ah[mt][2], ah[mt][3], ad);
                ldsm4(al[mt][0], al[mt][1], al[mt][2], al[mt][3], ad + 10240);
            }
#pragma unroll
            for (int np = 0; np < 4; np++) {
                int nrow = warpN * 64 + np * 16 + b_row;
                uint32_t bd = sbase + 20480 + (nrow * 40 + kk + b_k) * 2;
                uint32_t bh[4], bl[4];
                ldsm4(bh[0], bh[1], bh[2], bh[3], bd);
                ldsm4(bl[0], bl[1], bl[2], bl[3], bd + 10240);
#pragma unroll
                for (int nt = 0; nt < 2; nt++) {
#pragma unroll
                    for (int mt = 0; mt < 2; mt++) {
                        float* c = acc[mt][np * 2 + nt];
                        mma16816(c, ah[mt], bh[2 * nt], bh[2 * nt + 1]);
                        mma16816(c, ah[mt], bl[2 * nt], bl[2 * nt + 1]);
                        mma16816(c, al[mt], bh[2 * nt], bh[2 * nt + 1]);
                    }
                }
            }
        }
        __syncthreads();
    }

    // epilogue 1: write fp32 result row-major (coalesced from registers)
#pragma unroll
    for (int mt = 0; mt < 2; mt++) {
#pragma unroll
        for (int nid = 0; nid < 8; nid++) {
            int row = m0 + warpM * 32 + mt * 16 + (lane >> 2);
            int col = n0 + warpN * 64 + nid * 8 + (lane & 3) * 2;
            float* c = acc[mt][nid];
            float2 v0; v0.x = c[0]; v0.y = c[1];
            float2 v1; v1.x = c[2]; v1.y = c[3];
            *(float2*)&g_xin[row * DM + col]       = v0;
            *(float2*)&g_xin[(row + 8) * DM + col] = v1;
        }
    }

    // epilogue 2: fused transpose -> g_uT (b, d, t) via smem stage
    __syncthreads();   // done with mainloop smem
    float (*ysm)[129] = (float (*)[129])smem_raw;
#pragma unroll
    for (int mt = 0; mt < 2; mt++) {
#pragma unroll
        for (int nid = 0; nid < 8; nid++) {
            int rl = warpM * 32 + mt * 16 + (lane >> 2);
            int cl = warpN * 64 + nid * 8 + (lane & 3) * 2;
            float* c = acc[mt][nid];
            ysm[rl][cl]     = c[0];
            ysm[rl][cl + 1] = c[1];
            ysm[rl + 8][cl]     = c[2];
            ysm[rl + 8][cl + 1] = c[3];
        }
    }
    __syncthreads();
    {
        int b = m0 >> 11;          // 2048-aligned batch
        int t0 = m0 & 2047;
        for (int i = tid; i < 128 * 128; i += 256) {
            int n = i >> 7, m = i & 127;
            g_uT[((size_t)(b * 1024 + n0 + n)) * SSEQ + t0 + m] = ysm[m][n];
        }
    }
}

// ---------------- GEMM2: proj = x_in(4096x1024) @ w_x(1024x96) ----------------
__global__ __launch_bounds__(128) void proj_kernel(const float* __restrict__ w_x) {
    __shared__ float xs[4][1024];
    int r0 = blockIdx.x * 4;
    for (int i = threadIdx.x; i < 4 * 1024; i += 128)
        xs[i >> 10][i & 1023] = g_xin[(r0 + (i >> 10)) * DM + (i & 1023)];
    __syncthreads();
    int p = threadIdx.x;
    if (p < PP) {
        float a0 = 0.f, a1 = 0.f, a2 = 0.f, a3 = 0.f;
#pragma unroll 4
        for (int k = 0; k < 1024; k++) {
            float w = w_x[k * PP + p];
            a0 = fmaf(xs[0][k], w, a0);
            a1 = fmaf(xs[1][k], w, a1);
            a2 = fmaf(xs[2][k], w, a2);
            a3 = fmaf(xs[3][k], w, a3);
        }
        g_proj[(r0 + 0) * PP + p] = a0;
        g_proj[(r0 + 1) * PP + p] = a1;
        g_proj[(r0 + 2) * PP + p] = a2;
        g_proj[(r0 + 3) * PP + p] = a3;
    }
}

// ---------------- GEMM3 + softplus, fused dtT write ----------------
__global__ __launch_bounds__(256) void dtproj_kernel(const float* __restrict__ w_dt,
                                                     const float* __restrict__ b_dt) {
    __shared__ float Asm[32][64];
    __shared__ float Bsm[64][128];
    int row0 = blockIdx.y * 32, col0 = blockIdx.x * 128;
    int tid = threadIdx.x;
    for (int i = tid; i < 32 * 64; i += 256) {
        int rr = i >> 6, kk = i & 63;
        Asm[rr][kk] = g_proj[(row0 + rr) * PP + kk];
    }
    for (int i = tid; i < 64 * 128; i += 256) {
        int kk = i >> 7, cc = i & 127;
        Bsm[kk][cc] = w_dt[kk * DM + col0 + cc];
    }
    __syncthreads();
    int tx = tid & 15, ty = tid >> 4;
    float acc[2][8];
#pragma unroll
    for (int r = 0; r < 2; r++)
#pragma unroll
        for (int j = 0; j < 8; j++) acc[r][j] = 0.f;
#pragma unroll
    for (int k = 0; k < 64; k++) {
        float a0 = Asm[ty * 2][k], a1 = Asm[ty * 2 + 1][k];
        float4 bA = *(const float4*)&Bsm[k][tx * 8];
        float4 bB = *(const float4*)&Bsm[k][tx * 8 + 4];
        float bvals[8] = {bA.x, bA.y, bA.z, bA.w, bB.x, bB.y, bB.z, bB.w};
#pragma unroll
        for (int j = 0; j < 8; j++) {
            acc[0][j] = fmaf(a0, bvals[j], acc[0][j]);
            acc[1][j] = fmaf(a1, bvals[j], acc[1][j]);
        }
    }
    // softplus + store row-major, then stage for transposed store
    float vals[2][8];
#pragma unroll
    for (int rr = 0; rr < 2; rr++)
#pragma unroll
        for (int j = 0; j < 8; j++) {
            int col = col0 + tx * 8 + j;
            float v = acc[rr][j] + b_dt[col];
            float sp = (v > 20.f) ? v : log1pf(expf(v));
            float dt = sp * 0.099f + 0.001f;
            vals[rr][j] = dt;
            g_dt[(row0 + ty * 2 + rr) * DM + col] = dt;
        }
    __syncthreads();   // done reading Bsm; reuse as 32x129 stage
    float (*ysm)[129] = (float (*)[129])(&Bsm[0][0]);
#pragma unroll
    for (int rr = 0; rr < 2; rr++)
#pragma unroll
        for (int j = 0; j < 8; j++)
            ysm[ty * 2 + rr][tx * 8 + j] = vals[rr][j];
    __syncthreads();
    {
        int b = row0 >> 11;
        int t0 = row0 & 2047;
        for (int i = tid; i < 32 * 128; i += 256) {
            int dcol = i >> 5, m = i & 31;
            g_dtT[((size_t)(b * 1024 + col0 + dcol)) * SSEQ + t0 + m] = ysm[m][dcol];
        }
    }
}

// ---------------- G & inp ----------------
__global__ __launch_bounds__(512) void ginp_kernel() {
    int r = blockIdx.x;
    int tid = threadIdx.x;
    int n = tid & 15, dg = tid >> 4;  // dg: 0..31
    const float* dtr = g_dt + r * DM;
    const float* ur  = g_xin + r * DM;
    float partial = 0.f;
#pragma unroll 8
    for (int i = 0; i < 32; i++) {
        int d = dg + (i << 5);
        float s = dtr[d] * ur[d];
        partial = fmaf(s, g_Aneg[d * 16 + n], partial);
    }
    __shared__ float red[32][16];
    red[dg][n] = partial;
    __syncthreads();
    for (int s2 = 16; s2 > 0; s2 >>= 1) {
        if (dg < s2) red[dg][n] += red[dg + s2][n];
        __syncthreads();
    }
    if (tid < 16) {
        float G = red[0][tid];
        g_inp [r * NS + tid] = g_proj[r * PP + 64 + tid] * G;
        g_Cbuf[r * NS + tid] = g_proj[r * PP + 80 + tid];
    }
}

// ---------------- scan: writes final output (b, s, d) directly ----------------
// 16 lanes per (b,d) pair; y buffered in smem, flushed every 64 steps.
__global__ __launch_bounds__(128) void scan_kernel(const float* __restrict__ Dp,
                                                   float* __restrict__ outp) {
    __shared__ float ybuf[8][65];
    int lane = threadIdx.x & 15;
    int g    = threadIdx.x >> 4;                      // 0..7
    int pair = blockIdx.x * 8 + g;                    // pair = b*1024 + d
    int b = pair >> 10, d = pair & 1023;
    int d0 = (blockIdx.x * 8) & 1023;
    float An  = g_Aneg[d * 16 + lane];
    float Dpd = Dp[d];
    const float* dtp  = g_dtT + (size_t)pair * SSEQ;
    const float* up   = g_uT  + (size_t)pair * SSEQ;
    const float* inpp = g_inp  + (size_t)b * SSEQ * NS;
    const float* Cp   = g_Cbuf + (size_t)b * SSEQ * NS;
    float h = 0.f;
    for (int tc = 0; tc < SSEQ; tc += 64) {
#pragma unroll 4
        for (int tt = 0; tt < 64; tt++) {
            int t = tc + tt;
            float dtv = __ldg(&dtp[t]);
            float uv  = __ldg(&up[t]);
            float e   = __expf(dtv * An);
            float iv  = __ldg(&inpp[t * NS + lane]);
            float cv  = __ldg(&Cp[t * NS + lane]);
            h = fmaf(e, h, iv);
            float p = h * cv;
            p += __shfl_xor_sync(0xffffffffu, p, 1);
            p += __shfl_xor_sync(0xffffffffu, p, 2);
            p += __shfl_xor_sync(0xffffffffu, p, 4);
            p += __shfl_xor_sync(0xffffffffu, p, 8);
            if (lane == 0) ybuf[g][tt] = fmaf(Dpd, uv, p);
        }
        __syncthreads();
        for (int i = threadIdx.x; i < 512; i += 128) {
            int gg = i & 7, tt = i >> 3;
            outp[((size_t)(b * SSEQ + tc + tt)) * DM + d0 + gg] = ybuf[gg][tt];
        }
        __syncthreads();
    }
}

// ---------------- launch ----------------
extern "C" void kernel_launch(void* const* d_in, const int* in_sizes, int n_in,
                              void* d_out, int out_size) {
    const float* x     = (const float*)d_in[0];
    const float* w_in  = (const float*)d_in[1];
    const float* w_x   = (const float*)d_in[2];
    const float* w_dt  = (const float*)d_in[3];
    const float* b_dt  = (const float*)d_in[4];
    const float* A_log = (const float*)d_in[5];
    const float* Dp    = (const float*)d_in[6];
    float* out = (float*)d_out;

    cudaFuncSetAttribute(mma_gemm_kernel,
                         cudaFuncAttributeMaxDynamicSharedMemorySize, 81920);

    aneg_kernel<<<64, 256>>>(A_log);
    convert_x_kernel<<<4096, 256>>>(x);
    convert_w_kernel<<<dim3(32, 32), dim3(32, 8)>>>(w_in);
    mma_gemm_kernel<<<dim3(8, 32), 256, 81920>>>();
    proj_kernel<<<1024, 128>>>(w_x);
    dtproj_kernel<<<dim3(8, 128), 256>>>(w_dt, b_dt);
    ginp_kernel<<<4096, 512>>>();
    scan_kernel<<<256, 128>>>(Dp, out);
}

// round 10
// speedup vs baseline: 1.6184x; 1.6184x over previous
#include <cuda_runtime.h>
#include <cuda_bf16.h>
#include <cstdint>
#include <math.h>

#define RTOT 4096       // b*s
#define DM   1024
#define NS   16
#define PP   96
#define SSEQ 2048

// ---------------- scratch (device globals; no allocs allowed) ----------------
__device__ float g_xin [RTOT*DM];   // x @ w_in           (r, d)
__device__ float g_proj[RTOT*PP];   // x_in @ w_x         (r, 96)
__device__ float g_dt  [RTOT*DM];   // dt after softplus  (r, d)
__device__ float g_dtT [RTOT*DM];   // dt transposed      (b, d, t)
__device__ float g_uT  [RTOT*DM];   // x_in transposed    (b, d, t)
__device__ float g_yT  [RTOT*DM];   // y transposed       (b, d, t)
__device__ float g_inp [RTOT*NS];   // B * (s @ Aneg)     (r, n)
__device__ float g_Cbuf[RTOT*NS];   // packed C           (r, n)
__device__ float g_Aneg[DM*NS];     // -exp(A_log)
// bf16 split operands for tensor-core GEMM1
__device__ __nv_bfloat16 g_xh [RTOT*DM];   // hi(x)
__device__ __nv_bfloat16 g_xl [RTOT*DM];   // lo(x)
__device__ __nv_bfloat16 g_whT[DM*DM];     // hi(w_in)^T  [n][k]
__device__ __nv_bfloat16 g_wlT[DM*DM];     // lo(w_in)^T  [n][k]

// ---------------- A = -exp(A_log) ----------------
__global__ void aneg_kernel(const float* __restrict__ A_log) {
    int i = blockIdx.x * blockDim.x + threadIdx.x;
    if (i < DM * NS) g_Aneg[i] = -expf(A_log[i]);
}

// ---------------- convert x -> bf16 hi/lo (vectorized) ----------------
__global__ void convert_x_kernel(const float* __restrict__ x) {
    int i = blockIdx.x * 256 + threadIdx.x;       // handles 4 floats
    float4 v = ((const float4*)x)[i];
    __nv_bfloat16 h0 = __float2bfloat16(v.x);
    __nv_bfloat16 h1 = __float2bfloat16(v.y);
    __nv_bfloat16 h2 = __float2bfloat16(v.z);
    __nv_bfloat16 h3 = __float2bfloat16(v.w);
    __nv_bfloat16 l0 = __float2bfloat16(v.x - __bfloat162float(h0));
    __nv_bfloat16 l1 = __float2bfloat16(v.y - __bfloat162float(h1));
    __nv_bfloat16 l2 = __float2bfloat16(v.z - __bfloat162float(h2));
    __nv_bfloat16 l3 = __float2bfloat16(v.w - __bfloat162float(h3));
    __nv_bfloat162 ph0; ph0.x = h0; ph0.y = h1;
    __nv_bfloat162 ph1; ph1.x = h2; ph1.y = h3;
    __nv_bfloat162 pl0; pl0.x = l0; pl0.y = l1;
    __nv_bfloat162 pl1; pl1.x = l2; pl1.y = l3;
    __nv_bfloat162* ph = (__nv_bfloat162*)g_xh;
    __nv_bfloat162* pl = (__nv_bfloat162*)g_xl;
    ph[i * 2]     = ph0;
    ph[i * 2 + 1] = ph1;
    pl[i * 2]     = pl0;
    pl[i * 2 + 1] = pl1;
}

// ---------------- convert w_in -> transposed bf16 hi/lo ----------------
// w[k][n] (1024x1024) -> whT[n][k], wlT[n][k]
__global__ void convert_w_kernel(const float* __restrict__ w) {
    __shared__ float t[32][33];
    int kbase = blockIdx.y * 32, nbase = blockIdx.x * 32;
#pragma unroll
    for (int j = threadIdx.y; j < 32; j += 8)
        t[j][threadIdx.x] = w[(kbase + j) * DM + nbase + threadIdx.x];
    __syncthreads();
#pragma unroll
    for (int j = threadIdx.y; j < 32; j += 8) {
        float v = t[threadIdx.x][j];               // = w[kbase+tx][nbase+j]
        __nv_bfloat16 h = __float2bfloat16(v);
        __nv_bfloat16 l = __float2bfloat16(v - __bfloat162float(h));
        g_whT[(nbase + j) * DM + kbase + threadIdx.x] = h;
        g_wlT[(nbase + j) * DM + kbase + threadIdx.x] = l;
    }
}

// ---------------- tensor-core GEMM1 helpers ----------------
__device__ __forceinline__ void ldsm4(uint32_t& r0, uint32_t& r1, uint32_t& r2, uint32_t& r3,
                                      uint32_t addr) {
    asm volatile("ldmatrix.sync.aligned.m8n8.x4.shared.b16 {%0,%1,%2,%3},[%4];"
                 : "=r"(r0), "=r"(r1), "=r"(r2), "=r"(r3) : "r"(addr));
}
__device__ __forceinline__ void mma16816(float* c, const uint32_t* a, uint32_t b0, uint32_t b1) {
    asm volatile(
        "mma.sync.aligned.m16n8k16.row.col.f32.bf16.bf16.f32 "
        "{%0,%1,%2,%3},{%4,%5,%6,%7},{%8,%9},{%0,%1,%2,%3};"
        : "+f"(c[0]), "+f"(c[1]), "+f"(c[2]), "+f"(c[3])
        : "r"(a[0]), "r"(a[1]), "r"(a[2]), "r"(a[3]), "r"(b0), "r"(b1));
}
__device__ __forceinline__ void cp16(uint32_t saddr, const void* g) {
    asm volatile("cp.async.cg.shared.global [%0],[%1],16;" ::"r"(saddr), "l"(g) : "memory");
}
__device__ __forceinline__ void cp_commit() {
    asm volatile("cp.async.commit_group;" ::: "memory");
}

// issue async loads of one BK=32 stage (4 tiles of [128][40] bf16, 10240B each)
__device__ __forceinline__ void issue_stage(uint32_t smem_u32, int tid,
                                            const __nv_bfloat16* s0, const __nv_bfloat16* s1,
                                            const __nv_bfloat16* s2, const __nv_bfloat16* s3,
                                            int stage, int k0) {
    uint32_t sbase = smem_u32 + stage * 40960;
    const __nv_bfloat16* srcs[4];
    srcs[0] = s0; srcs[1] = s1; srcs[2] = s2; srcs[3] = s3;
#pragma unroll
    for (int tile = 0; tile < 4; tile++) {
        const __nv_bfloat16* src = srcs[tile];
        uint32_t toff = sbase + tile * 10240;
#pragma unroll
        for (int i = 0; i < 2; i++) {
            int c = tid + i * 256;
            int row = c >> 2, q = c & 3;
            cp16(toff + row * 80 + q * 16, src + row * DM + k0 + q * 8);
        }
    }
    cp_commit();
}

// smem per stage: tiles 0=Ah 1=Al 2=Bh 3=Bl; stage stride 40960B; total 81920B
// epilogue reuses smem as float[128][129] transpose stage (66048B <= 81920B)
__global__ __launch_bounds__(256) void mma_gemm_kernel() {
    extern __shared__ __align__(16) char smem_raw[];
    uint32_t smem_u32 = (uint32_t)__cvta_generic_to_shared(smem_raw);

    int tid = threadIdx.x;
    int wid = tid >> 5, lane = tid & 31;
    int warpM = wid & 3, warpN = wid >> 2;
    int m0 = blockIdx.y * 128;
    int n0 = blockIdx.x * 128;

    const __nv_bfloat16* sxh = g_xh + (size_t)m0 * DM;
    const __nv_bfloat16* sxl = g_xl + (size_t)m0 * DM;
    const __nv_bfloat16* swh = g_whT + (size_t)n0 * DM;
    const __nv_bfloat16* swl = g_wlT + (size_t)n0 * DM;

    float acc[2][8][4];
#pragma unroll
    for (int mt = 0; mt < 2; mt++)
#pragma unroll
        for (int nt = 0; nt < 8; nt++)
#pragma unroll
            for (int e = 0; e < 4; e++) acc[mt][nt][e] = 0.f;

    // ldmatrix per-lane address components
    int a_row = lane & 15;
    int a_k   = (lane >> 4) << 3;
    int b_row = (lane & 7) + ((lane >> 4) << 3);
    int b_k   = ((lane >> 3) & 1) << 3;

    issue_stage(smem_u32, tid, sxh, sxl, swh, swl, 0, 0);

    const int NK = 32;  // 1024 / 32
    for (int kt = 0; kt < NK; kt++) {
        if (kt + 1 < NK) {
            issue_stage(smem_u32, tid, sxh, sxl, swh, swl, (kt + 1) & 1, (kt + 1) * 32);
            asm volatile("cp.async.wait_group 1;" ::: "memory");
        } else {
            asm volatile("cp.async.wait_group 0;" ::: "memory");
        }
        __syncthreads();

        uint32_t sbase = smem_u32 + (kt & 1) * 40960;
#pragma unroll
        for (int ks = 0; ks < 2; ks++) {
            int kk = ks * 16;
            uint32_t ah[2][4], al[2][4];
#pragma unroll
            for (int mt = 0; mt < 2; mt++) {
                int mrow = warpM * 32 + mt * 16 + a_row;
                uint32_t ad = sbase + (mrow * 40 + kk + a_k) * 2;
                ldsm4(ah[mt][0], ah[mt][1], ah[mt][2], ah[mt][3], ad);
                ldsm4(al[mt][0], al[mt][1], al[mt][2], al[mt][3], ad + 10240);
            }
#pragma unroll
            for (int np = 0; np < 4; np++) {
                int nrow = warpN * 64 + np * 16 + b_row;
                uint32_t bd = sbase + 20480 + (nrow * 40 + kk + b_k) * 2;
                uint32_t bh[4], bl[4];
                ldsm4(bh[0], bh[1], bh[2], bh[3], bd);
                ldsm4(bl[0], bl[1], bl[2], bl[3], bd + 10240);
#pragma unroll
                for (int nt = 0; nt < 2; nt++) {
#pragma unroll
                    for (int mt = 0; mt < 2; mt++) {
                        float* c = acc[mt][np * 2 + nt];
                        mma16816(c, ah[mt], bh[2 * nt], bh[2 * nt + 1]);
                        mma16816(c, ah[mt], bl[2 * nt], bl[2 * nt + 1]);
                        mma16816(c, al[mt], bh[2 * nt], bh[2 * nt + 1]);
                    }
                }
            }
        }
        __syncthreads();
    }

    // epilogue 1: write fp32 result row-major (coalesced from registers)
#pragma unroll
    for (int mt = 0; mt < 2; mt++) {
#pragma unroll
        for (int nid = 0; nid < 8; nid++) {
            int row = m0 + warpM * 32 + mt * 16 + (lane >> 2);
            int col = n0 + warpN * 64 + nid * 8 + (lane & 3) * 2;
            float* c = acc[mt][nid];
            float2 v0; v0.x = c[0]; v0.y = c[1];
            float2 v1; v1.x = c[2]; v1.y = c[3];
            *(float2*)&g_xin[row * DM + col]       = v0;
            *(float2*)&g_xin[(row + 8) * DM + col] = v1;
        }
    }

    // epilogue 2: fused transpose -> g_uT (b, d, t) via smem stage
    __syncthreads();   // done with mainloop smem
    float (*ysm)[129] = (float (*)[129])smem_raw;
#pragma unroll
    for (int mt = 0; mt < 2; mt++) {
#pragma unroll
        for (int nid = 0; nid < 8; nid++) {
            int rl = warpM * 32 + mt * 16 + (lane >> 2);
            int cl = warpN * 64 + nid * 8 + (lane & 3) * 2;
            float* c = acc[mt][nid];
            ysm[rl][cl]     = c[0];
            ysm[rl][cl + 1] = c[1];
            ysm[rl + 8][cl]     = c[2];
            ysm[rl + 8][cl + 1] = c[3];
        }
    }
    __syncthreads();
    {
        int b = m0 >> 11;          // 2048-aligned batch
        int t0 = m0 & 2047;
        for (int i = tid; i < 128 * 128; i += 256) {
            int n = i >> 7, m = i & 127;
            g_uT[((size_t)(b * 1024 + n0 + n)) * SSEQ + t0 + m] = ysm[m][n];
        }
    }
}

// ---------------- GEMM2: proj = x_in(4096x1024) @ w_x(1024x96) ----------------
__global__ __launch_bounds__(128) void proj_kernel(const float* __restrict__ w_x) {
    __shared__ float xs[4][1024];
    int r0 = blockIdx.x * 4;
    for (int i = threadIdx.x; i < 4 * 1024; i += 128)
        xs[i >> 10][i & 1023] = g_xin[(r0 + (i >> 10)) * DM + (i & 1023)];
    __syncthreads();
    int p = threadIdx.x;
    if (p < PP) {
        float a0 = 0.f, a1 = 0.f, a2 = 0.f, a3 = 0.f;
#pragma unroll 4
        for (int k = 0; k < 1024; k++) {
            float w = w_x[k * PP + p];
            a0 = fmaf(xs[0][k], w, a0);
            a1 = fmaf(xs[1][k], w, a1);
            a2 = fmaf(xs[2][k], w, a2);
            a3 = fmaf(xs[3][k], w, a3);
        }
        g_proj[(r0 + 0) * PP + p] = a0;
        g_proj[(r0 + 1) * PP + p] = a1;
        g_proj[(r0 + 2) * PP + p] = a2;
        g_proj[(r0 + 3) * PP + p] = a3;
    }
}

// ---------------- GEMM3 + softplus, fused dtT write ----------------
__global__ __launch_bounds__(256) void dtproj_kernel(const float* __restrict__ w_dt,
                                                     const float* __restrict__ b_dt) {
    __shared__ float Asm[32][64];
    __shared__ float Bsm[64][128];
    int row0 = blockIdx.y * 32, col0 = blockIdx.x * 128;
    int tid = threadIdx.x;
    for (int i = tid; i < 32 * 64; i += 256) {
        int rr = i >> 6, kk = i & 63;
        Asm[rr][kk] = g_proj[(row0 + rr) * PP + kk];
    }
    for (int i = tid; i < 64 * 128; i += 256) {
        int kk = i >> 7, cc = i & 127;
        Bsm[kk][cc] = w_dt[kk * DM + col0 + cc];
    }
    __syncthreads();
    int tx = tid & 15, ty = tid >> 4;
    float acc[2][8];
#pragma unroll
    for (int r = 0; r < 2; r++)
#pragma unroll
        for (int j = 0; j < 8; j++) acc[r][j] = 0.f;
#pragma unroll
    for (int k = 0; k < 64; k++) {
        float a0 = Asm[ty * 2][k], a1 = Asm[ty * 2 + 1][k];
        float4 bA = *(const float4*)&Bsm[k][tx * 8];
        float4 bB = *(const float4*)&Bsm[k][tx * 8 + 4];
        float bvals[8] = {bA.x, bA.y, bA.z, bA.w, bB.x, bB.y, bB.z, bB.w};
#pragma unroll
        for (int j = 0; j < 8; j++) {
            acc[0][j] = fmaf(a0, bvals[j], acc[0][j]);
            acc[1][j] = fmaf(a1, bvals[j], acc[1][j]);
        }
    }
    // softplus + store row-major, then stage for transposed store
    float vals[2][8];
#pragma unroll
    for (int rr = 0; rr < 2; rr++)
#pragma unroll
        for (int j = 0; j < 8; j++) {
            int col = col0 + tx * 8 + j;
            float v = acc[rr][j] + b_dt[col];
            float sp = (v > 20.f) ? v : log1pf(expf(v));
            float dt = sp * 0.099f + 0.001f;
            vals[rr][j] = dt;
            g_dt[(row0 + ty * 2 + rr) * DM + col] = dt;
        }
    __syncthreads();   // done reading Bsm; reuse as 32x129 stage
    float (*ysm)[129] = (float (*)[129])(&Bsm[0][0]);
#pragma unroll
    for (int rr = 0; rr < 2; rr++)
#pragma unroll
        for (int j = 0; j < 8; j++)
            ysm[ty * 2 + rr][tx * 8 + j] = vals[rr][j];
    __syncthreads();
    {
        int b = row0 >> 11;
        int t0 = row0 & 2047;
        for (int i = tid; i < 32 * 128; i += 256) {
            int dcol = i >> 5, m = i & 31;
            g_dtT[((size_t)(b * 1024 + col0 + dcol)) * SSEQ + t0 + m] = ysm[m][dcol];
        }
    }
}

// ---------------- G & inp ----------------
__global__ __launch_bounds__(512) void ginp_kernel() {
    int r = blockIdx.x;
    int tid = threadIdx.x;
    int n = tid & 15, dg = tid >> 4;  // dg: 0..31
    const float* dtr = g_dt + r * DM;
    const float* ur  = g_xin + r * DM;
    float partial = 0.f;
#pragma unroll 8
    for (int i = 0; i < 32; i++) {
        int d = dg + (i << 5);
        float s = dtr[d] * ur[d];
        partial = fmaf(s, g_Aneg[d * 16 + n], partial);
    }
    __shared__ float red[32][16];
    red[dg][n] = partial;
    __syncthreads();
    for (int s2 = 16; s2 > 0; s2 >>= 1) {
        if (dg < s2) red[dg][n] += red[dg + s2][n];
        __syncthreads();
    }
    if (tid < 16) {
        float G = red[0][tid];
        g_inp [r * NS + tid] = g_proj[r * PP + 64 + tid] * G;
        g_Cbuf[r * NS + tid] = g_proj[r * PP + 80 + tid];
    }
}

// ---------------- scan: h = exp(dt*A)*h + inp; y = sum_n h*C + Dp*u ----------------
// round-8 form: writes g_yT sequential-in-t (known-good performance)
__global__ __launch_bounds__(128) void scan_kernel(const float* __restrict__ Dp) {
    int lane = threadIdx.x & 15;
    int pair = blockIdx.x * 8 + (threadIdx.x >> 4);   // pair = b*1024 + d
    int b = pair >> 10, d = pair & 1023;
    float An  = g_Aneg[d * 16 + lane];
    float Dpd = Dp[d];
    const float* dtp  = g_dtT + (size_t)pair * SSEQ;
    const float* up   = g_uT  + (size_t)pair * SSEQ;
    const float* inpp = g_inp  + (size_t)b * SSEQ * NS;
    const float* Cp   = g_Cbuf + (size_t)b * SSEQ * NS;
    float* yp = g_yT + (size_t)pair * SSEQ;
    float h = 0.f;
#pragma unroll 4
    for (int t = 0; t < SSEQ; t++) {
        float dtv = __ldg(&dtp[t]);
        float uv  = __ldg(&up[t]);
        float e   = __expf(dtv * An);
        float iv  = __ldg(&inpp[t * NS + lane]);
        float cv  = __ldg(&Cp[t * NS + lane]);
        h = fmaf(e, h, iv);
        float p = h * cv;
        p += __shfl_xor_sync(0xffffffffu, p, 1);
        p += __shfl_xor_sync(0xffffffffu, p, 2);
        p += __shfl_xor_sync(0xffffffffu, p, 4);
        p += __shfl_xor_sync(0xffffffffu, p, 8);
        if (lane == 0) yp[t] = fmaf(Dpd, uv, p);
    }
}

// ---------------- output transpose: g_yT (1024x2048) -> out (2048x1024) ----------------
__global__ void transpose_out_kernel(float* __restrict__ outp) {
    const int rows = 1024, cols = 2048;
    __shared__ float tile[32][33];
    const float* s = g_yT + blockIdx.z * rows * cols;
    float* o = outp + blockIdx.z * rows * cols;
    int x = blockIdx.x * 32 + threadIdx.x;
    int y0 = blockIdx.y * 32;
#pragma unroll
    for (int j = threadIdx.y; j < 32; j += 8)
        tile[j][threadIdx.x] = s[(y0 + j) * cols + x];
    __syncthreads();
    int xr = y0 + threadIdx.x;
    int yc0 = blockIdx.x * 32;
#pragma unroll
    for (int j = threadIdx.y; j < 32; j += 8)
        o[(yc0 + j) * rows + xr] = tile[threadIdx.x][j];
}

// ---------------- launch ----------------
// NOTE: launch order chosen so slot #3 (the ncu-profiled launch) = proj_kernel.
extern "C" void kernel_launch(void* const* d_in, const int* in_sizes, int n_in,
                              void* d_out, int out_size) {
    const float* x     = (const float*)d_in[0];
    const float* w_in  = (const float*)d_in[1];
    const float* w_x   = (const float*)d_in[2];
    const float* w_dt  = (const float*)d_in[3];
    const float* b_dt  = (const float*)d_in[4];
    const float* A_log = (const float*)d_in[5];
    const float* Dp    = (const float*)d_in[6];
    float* out = (float*)d_out;

    cudaFuncSetAttribute(mma_gemm_kernel,
                         cudaFuncAttributeMaxDynamicSharedMemorySize, 81920);

    convert_x_kernel<<<4096, 256>>>(x);                     // 0
    convert_w_kernel<<<dim3(32, 32), dim3(32, 8)>>>(w_in);  // 1
    mma_gemm_kernel<<<dim3(8, 32), 256, 81920>>>();         // 2
    proj_kernel<<<1024, 128>>>(w_x);                        // 3  <- profiled slot
    aneg_kernel<<<64, 256>>>(A_log);                        // 4
    dtproj_kernel<<<dim3(8, 128), 256>>>(w_dt, b_dt);       // 5
    ginp_kernel<<<4096, 512>>>();                           // 6
    scan_kernel<<<256, 128>>>(Dp);                          // 7
    transpose_out_kernel<<<dim3(64, 32, 2), dim3(32, 8)>>>(out); // 8
}

// round 11
// speedup vs baseline: 1.9001x; 1.1741x over previous
#include <cuda_runtime.h>
#include <cuda_bf16.h>
#include <cstdint>
#include <math.h>

#define RTOT 4096       // b*s
#define DM   1024
#define NS   16
#define PP   96
#define SSEQ 2048

// ---------------- scratch (device globals; no allocs allowed) ----------------
__device__ float g_xin [RTOT*DM];   // x @ w_in           (r, d)
__device__ float g_proj[RTOT*PP];   // x_in @ w_x         (r, 96)
__device__ float g_dt  [RTOT*DM];   // dt after softplus  (r, d)
__device__ float g_dtT [RTOT*DM];   // dt transposed      (b, d, t)
__device__ float g_uT  [RTOT*DM];   // x_in transposed    (b, d, t)
__device__ float g_yT  [RTOT*DM];   // y transposed       (b, d, t)
__device__ float g_inp [RTOT*NS];   // B * (s @ Aneg)     (r, n)
__device__ float g_Cbuf[RTOT*NS];   // packed C           (r, n)
__device__ float g_Aneg[DM*NS];     // -exp(A_log)
__device__ float g_ppart[4*RTOT*128]; // proj split-K partials
// bf16 split operands
__device__ __nv_bfloat16 g_xh  [RTOT*DM];  // hi(x)
__device__ __nv_bfloat16 g_xl  [RTOT*DM];  // lo(x)
__device__ __nv_bfloat16 g_whT [DM*DM];    // hi(w_in)^T  [n][k]
__device__ __nv_bfloat16 g_wlT [DM*DM];    // lo(w_in)^T  [n][k]
__device__ __nv_bfloat16 g_xinh[RTOT*DM];  // hi(x_in)
__device__ __nv_bfloat16 g_xinl[RTOT*DM];  // lo(x_in)
__device__ __nv_bfloat16 g_wxTh[128*DM];   // hi(w_x)^T [128(pad)][1024]
__device__ __nv_bfloat16 g_wxTl[128*DM];   // lo(w_x)^T

// ---------------- A = -exp(A_log) ----------------
__global__ void aneg_kernel(const float* __restrict__ A_log) {
    int i = blockIdx.x * blockDim.x + threadIdx.x;
    if (i < DM * NS) g_Aneg[i] = -expf(A_log[i]);
}

// ---------------- convert x -> bf16 hi/lo (vectorized) ----------------
__global__ void convert_x_kernel(const float* __restrict__ x) {
    int i = blockIdx.x * 256 + threadIdx.x;       // handles 4 floats
    float4 v = ((const float4*)x)[i];
    __nv_bfloat16 h0 = __float2bfloat16(v.x);
    __nv_bfloat16 h1 = __float2bfloat16(v.y);
    __nv_bfloat16 h2 = __float2bfloat16(v.z);
    __nv_bfloat16 h3 = __float2bfloat16(v.w);
    __nv_bfloat16 l0 = __float2bfloat16(v.x - __bfloat162float(h0));
    __nv_bfloat16 l1 = __float2bfloat16(v.y - __bfloat162float(h1));
    __nv_bfloat16 l2 = __float2bfloat16(v.z - __bfloat162float(h2));
    __nv_bfloat16 l3 = __float2bfloat16(v.w - __bfloat162float(h3));
    __nv_bfloat162 ph0; ph0.x = h0; ph0.y = h1;
    __nv_bfloat162 ph1; ph1.x = h2; ph1.y = h3;
    __nv_bfloat162 pl0; pl0.x = l0; pl0.y = l1;
    __nv_bfloat162 pl1; pl1.x = l2; pl1.y = l3;
    __nv_bfloat162* ph = (__nv_bfloat162*)g_xh;
    __nv_bfloat162* pl = (__nv_bfloat162*)g_xl;
    ph[i * 2]     = ph0;
    ph[i * 2 + 1] = ph1;
    pl[i * 2]     = pl0;
    pl[i * 2 + 1] = pl1;
}

// ---------------- convert w_in -> transposed bf16 hi/lo ----------------
__global__ void convert_w_kernel(const float* __restrict__ w) {
    __shared__ float t[32][33];
    int kbase = blockIdx.y * 32, nbase = blockIdx.x * 32;
#pragma unroll
    for (int j = threadIdx.y; j < 32; j += 8)
        t[j][threadIdx.x] = w[(kbase + j) * DM + nbase + threadIdx.x];
    __syncthreads();
#pragma unroll
    for (int j = threadIdx.y; j < 32; j += 8) {
        float v = t[threadIdx.x][j];
        __nv_bfloat16 h = __float2bfloat16(v);
        __nv_bfloat16 l = __float2bfloat16(v - __bfloat162float(h));
        g_whT[(nbase + j) * DM + kbase + threadIdx.x] = h;
        g_wlT[(nbase + j) * DM + kbase + threadIdx.x] = l;
    }
}

// ---------------- convert w_x -> transposed bf16 hi/lo, rows 96-127 zeroed ----
// w_x [1024][96] -> wxT[n][k]; grid (32 kblocks, 4 nblocks), block (32,8)
__global__ void convert_wx_kernel(const float* __restrict__ wx) {
    __shared__ float t[32][33];
    int kbase = blockIdx.x * 32, nbase = blockIdx.y * 32;
    if (nbase < PP) {
#pragma unroll
        for (int j = threadIdx.y; j < 32; j += 8)
            t[j][threadIdx.x] = wx[(kbase + j) * PP + nbase + threadIdx.x];
        __syncthreads();
#pragma unroll
        for (int j = threadIdx.y; j < 32; j += 8) {
            float v = t[threadIdx.x][j];
            __nv_bfloat16 h = __float2bfloat16(v);
            __nv_bfloat16 l = __float2bfloat16(v - __bfloat162float(h));
            g_wxTh[(nbase + j) * DM + kbase + threadIdx.x] = h;
            g_wxTl[(nbase + j) * DM + kbase + threadIdx.x] = l;
        }
    } else {
        __nv_bfloat16 z = __float2bfloat16(0.f);
#pragma unroll
        for (int j = threadIdx.y; j < 32; j += 8) {
            g_wxTh[(nbase + j) * DM + kbase + threadIdx.x] = z;
            g_wxTl[(nbase + j) * DM + kbase + threadIdx.x] = z;
        }
    }
}

// ---------------- tensor-core helpers ----------------
__device__ __forceinline__ void ldsm4(uint32_t& r0, uint32_t& r1, uint32_t& r2, uint32_t& r3,
                                      uint32_t addr) {
    asm volatile("ldmatrix.sync.aligned.m8n8.x4.shared.b16 {%0,%1,%2,%3},[%4];"
                 : "=r"(r0), "=r"(r1), "=r"(r2), "=r"(r3) : "r"(addr));
}
__device__ __forceinline__ void mma16816(float* c, const uint32_t* a, uint32_t b0, uint32_t b1) {
    asm volatile(
        "mma.sync.aligned.m16n8k16.row.col.f32.bf16.bf16.f32 "
        "{%0,%1,%2,%3},{%4,%5,%6,%7},{%8,%9},{%0,%1,%2,%3};"
        : "+f"(c[0]), "+f"(c[1]), "+f"(c[2]), "+f"(c[3])
        : "r"(a[0]), "r"(a[1]), "r"(a[2]), "r"(a[3]), "r"(b0), "r"(b1));
}
__device__ __forceinline__ void cp16(uint32_t saddr, const void* g) {
    asm volatile("cp.async.cg.shared.global [%0],[%1],16;" ::"r"(saddr), "l"(g) : "memory");
}
__device__ __forceinline__ void cp_commit() {
    asm volatile("cp.async.commit_group;" ::: "memory");
}

__device__ __forceinline__ void issue_stage(uint32_t smem_u32, int tid,
                                            const __nv_bfloat16* s0, const __nv_bfloat16* s1,
                                            const __nv_bfloat16* s2, const __nv_bfloat16* s3,
                                            int stage, int k0) {
    uint32_t sbase = smem_u32 + stage * 40960;
    const __nv_bfloat16* srcs[4];
    srcs[0] = s0; srcs[1] = s1; srcs[2] = s2; srcs[3] = s3;
#pragma unroll
    for (int tile = 0; tile < 4; tile++) {
        const __nv_bfloat16* src = srcs[tile];
        uint32_t toff = sbase + tile * 10240;
#pragma unroll
        for (int i = 0; i < 2; i++) {
            int c = tid + i * 256;
            int row = c >> 2, q = c & 3;
            cp16(toff + row * 80 + q * 16, src + row * DM + k0 + q * 8);
        }
    }
    cp_commit();
}

// core 128x128xK mainloop over 3-term split; acc[2][8][4]
__device__ __forceinline__ void mma_mainloop(uint32_t smem_u32, int tid, int wid, int lane,
                                             const __nv_bfloat16* sAh, const __nv_bfloat16* sAl,
                                             const __nv_bfloat16* sBh, const __nv_bfloat16* sBl,
                                             int kbase, int NK, float acc[2][8][4]) {
    int warpM = wid & 3, warpN = wid >> 2;
    int a_row = lane & 15;
    int a_k   = (lane >> 4) << 3;
    int b_row = (lane & 7) + ((lane >> 4) << 3);
    int b_k   = ((lane >> 3) & 1) << 3;

    issue_stage(smem_u32, tid, sAh, sAl, sBh, sBl, 0, kbase);

    for (int kt = 0; kt < NK; kt++) {
        if (kt + 1 < NK) {
            issue_stage(smem_u32, tid, sAh, sAl, sBh, sBl, (kt + 1) & 1, kbase + (kt + 1) * 32);
            asm volatile("cp.async.wait_group 1;" ::: "memory");
        } else {
            asm volatile("cp.async.wait_group 0;" ::: "memory");
        }
        __syncthreads();

        uint32_t sbase = smem_u32 + (kt & 1) * 40960;
#pragma unroll
        for (int ks = 0; ks < 2; ks++) {
            int kk = ks * 16;
            uint32_t ah[2][4], al[2][4];
#pragma unroll
            for (int mt = 0; mt < 2; mt++) {
                int mrow = warpM * 32 + mt * 16 + a_row;
                uint32_t ad = sbase + (mrow * 40 + kk + a_k) * 2;
                ldsm4(ah[mt][0], ah[mt][1], ah[mt][2], ah[mt][3], ad);
                ldsm4(al[mt][0], al[mt][1], al[mt][2], al[mt][3], ad + 10240);
            }
#pragma unroll
            for (int np = 0; np < 4; np++) {
                int nrow = warpN * 64 + np * 16 + b_row;
                uint32_t bd = sbase + 20480 + (nrow * 40 + kk + b_k) * 2;
                uint32_t bh[4], bl[4];
                ldsm4(bh[0], bh[1], bh[2], bh[3], bd);
                ldsm4(bl[0], bl[1], bl[2], bl[3], bd + 10240);
#pragma unroll
                for (int nt = 0; nt < 2; nt++) {
#pragma unroll
                    for (int mt = 0; mt < 2; mt++) {
                        float* c = acc[mt][np * 2 + nt];
                        mma16816(c, ah[mt], bh[2 * nt], bh[2 * nt + 1]);
                        mma16816(c, ah[mt], bl[2 * nt], bl[2 * nt + 1]);
                        mma16816(c, al[mt], bh[2 * nt], bh[2 * nt + 1]);
                    }
                }
            }
        }
        __syncthreads();
    }
}

// ---------------- GEMM1: x_in = x @ w_in ----------------
// epilogues: fp32 row-major, bf16 hi/lo row-major, fp32 transposed (g_uT)
__global__ __launch_bounds__(256) void mma_gemm_kernel() {
    extern __shared__ __align__(16) char smem_raw[];
    uint32_t smem_u32 = (uint32_t)__cvta_generic_to_shared(smem_raw);
    int tid = threadIdx.x;
    int wid = tid >> 5, lane = tid & 31;
    int warpM = wid & 3, warpN = wid >> 2;
    int m0 = blockIdx.y * 128;
    int n0 = blockIdx.x * 128;

    float acc[2][8][4];
#pragma unroll
    for (int mt = 0; mt < 2; mt++)
#pragma unroll
        for (int nt = 0; nt < 8; nt++)
#pragma unroll
            for (int e = 0; e < 4; e++) acc[mt][nt][e] = 0.f;

    mma_mainloop(smem_u32, tid, wid, lane,
                 g_xh + (size_t)m0 * DM, g_xl + (size_t)m0 * DM,
                 g_whT + (size_t)n0 * DM, g_wlT + (size_t)n0 * DM,
                 0, 32, acc);

    // epilogue 1: fp32 row-major + bf16 hi/lo row-major
#pragma unroll
    for (int mt = 0; mt < 2; mt++) {
#pragma unroll
        for (int nid = 0; nid < 8; nid++) {
            int row = m0 + warpM * 32 + mt * 16 + (lane >> 2);
            int col = n0 + warpN * 64 + nid * 8 + (lane & 3) * 2;
            float* c = acc[mt][nid];
            float2 v0; v0.x = c[0]; v0.y = c[1];
            float2 v1; v1.x = c[2]; v1.y = c[3];
            *(float2*)&g_xin[row * DM + col]       = v0;
            *(float2*)&g_xin[(row + 8) * DM + col] = v1;
            // bf16 split
            __nv_bfloat16 h0 = __float2bfloat16(c[0]);
            __nv_bfloat16 h1 = __float2bfloat16(c[1]);
            __nv_bfloat16 h2 = __float2bfloat16(c[2]);
            __nv_bfloat16 h3 = __float2bfloat16(c[3]);
            __nv_bfloat162 hh0; hh0.x = h0; hh0.y = h1;
            __nv_bfloat162 hh1; hh1.x = h2; hh1.y = h3;
            __nv_bfloat162 ll0;
            ll0.x = __float2bfloat16(c[0] - __bfloat162float(h0));
            ll0.y = __float2bfloat16(c[1] - __bfloat162float(h1));
            __nv_bfloat162 ll1;
            ll1.x = __float2bfloat16(c[2] - __bfloat162float(h2));
            ll1.y = __float2bfloat16(c[3] - __bfloat162float(h3));
            *(__nv_bfloat162*)&g_xinh[row * DM + col]       = hh0;
            *(__nv_bfloat162*)&g_xinh[(row + 8) * DM + col] = hh1;
            *(__nv_bfloat162*)&g_xinl[row * DM + col]       = ll0;
            *(__nv_bfloat162*)&g_xinl[(row + 8) * DM + col] = ll1;
        }
    }

    // epilogue 2: fused transpose -> g_uT via smem stage
    __syncthreads();
    float (*ysm)[129] = (float (*)[129])smem_raw;
#pragma unroll
    for (int mt = 0; mt < 2; mt++) {
#pragma unroll
        for (int nid = 0; nid < 8; nid++) {
            int rl = warpM * 32 + mt * 16 + (lane >> 2);
            int cl = warpN * 64 + nid * 8 + (lane & 3) * 2;
            float* c = acc[mt][nid];
            ysm[rl][cl]     = c[0];
            ysm[rl][cl + 1] = c[1];
            ysm[rl + 8][cl]     = c[2];
            ysm[rl + 8][cl + 1] = c[3];
        }
    }
    __syncthreads();
    {
        int b = m0 >> 11;
        int t0 = m0 & 2047;
        for (int i = tid; i < 128 * 128; i += 256) {
            int n = i >> 7, m = i & 127;
            g_uT[((size_t)(b * 1024 + n0 + n)) * SSEQ + t0 + m] = ysm[m][n];
        }
    }
}

// ---------------- proj via split-K MMA: grid (4 ksplits, 32 mtiles) ----------
__global__ __launch_bounds__(256) void proj_mma_kernel() {
    extern __shared__ __align__(16) char smem_raw[];
    uint32_t smem_u32 = (uint32_t)__cvta_generic_to_shared(smem_raw);
    int tid = threadIdx.x;
    int wid = tid >> 5, lane = tid & 31;
    int warpM = wid & 3, warpN = wid >> 2;
    int ks = blockIdx.x;
    int m0 = blockIdx.y * 128;

    float acc[2][8][4];
#pragma unroll
    for (int mt = 0; mt < 2; mt++)
#pragma unroll
        for (int nt = 0; nt < 8; nt++)
#pragma unroll
            for (int e = 0; e < 4; e++) acc[mt][nt][e] = 0.f;

    mma_mainloop(smem_u32, tid, wid, lane,
                 g_xinh + (size_t)m0 * DM, g_xinl + (size_t)m0 * DM,
                 g_wxTh, g_wxTl,
                 ks * 256, 8, acc);

    float* pbase = g_ppart + (size_t)ks * RTOT * 128;
#pragma unroll
    for (int mt = 0; mt < 2; mt++) {
#pragma unroll
        for (int nid = 0; nid < 8; nid++) {
            int row = m0 + warpM * 32 + mt * 16 + (lane >> 2);
            int col = warpN * 64 + nid * 8 + (lane & 3) * 2;
            float* c = acc[mt][nid];
            float2 v0; v0.x = c[0]; v0.y = c[1];
            float2 v1; v1.x = c[2]; v1.y = c[3];
            *(float2*)&pbase[(size_t)row * 128 + col]       = v0;
            *(float2*)&pbase[(size_t)(row + 8) * 128 + col] = v1;
        }
    }
}

// ---------------- proj reduce: sum 4 partials -> g_proj [r][96] -------------
__global__ __launch_bounds__(256) void proj_reduce_kernel() {
    int r0 = blockIdx.x * 8;
    for (int i = threadIdx.x; i < 8 * PP; i += 256) {
        int r = r0 + i / PP, p = i % PP;
        size_t idx = (size_t)r * 128 + p;
        float s = g_ppart[idx] + g_ppart[(size_t)RTOT * 128 + idx]
                + g_ppart[(size_t)2 * RTOT * 128 + idx]
                + g_ppart[(size_t)3 * RTOT * 128 + idx];
        g_proj[r * PP + p] = s;
    }
}

// ---------------- GEMM3 + softplus, fused dtT write ----------------
__global__ __launch_bounds__(256) void dtproj_kernel(const float* __restrict__ w_dt,
                                                     const float* __restrict__ b_dt) {
    __shared__ float Asm[32][64];
    __shared__ float Bsm[64][128];
    int row0 = blockIdx.y * 32, col0 = blockIdx.x * 128;
    int tid = threadIdx.x;
    for (int i = tid; i < 32 * 64; i += 256) {
        int rr = i >> 6, kk = i & 63;
        Asm[rr][kk] = g_proj[(row0 + rr) * PP + kk];
    }
    for (int i = tid; i < 64 * 128; i += 256) {
        int kk = i >> 7, cc = i & 127;
        Bsm[kk][cc] = w_dt[kk * DM + col0 + cc];
    }
    __syncthreads();
    int tx = tid & 15, ty = tid >> 4;
    float acc[2][8];
#pragma unroll
    for (int r = 0; r < 2; r++)
#pragma unroll
        for (int j = 0; j < 8; j++) acc[r][j] = 0.f;
#pragma unroll
    for (int k = 0; k < 64; k++) {
        float a0 = Asm[ty * 2][k], a1 = Asm[ty * 2 + 1][k];
        float4 bA = *(const float4*)&Bsm[k][tx * 8];
        float4 bB = *(const float4*)&Bsm[k][tx * 8 + 4];
        float bvals[8] = {bA.x, bA.y, bA.z, bA.w, bB.x, bB.y, bB.z, bB.w};
#pragma unroll
        for (int j = 0; j < 8; j++) {
            acc[0][j] = fmaf(a0, bvals[j], acc[0][j]);
            acc[1][j] = fmaf(a1, bvals[j], acc[1][j]);
        }
    }
    float vals[2][8];
#pragma unroll
    for (int rr = 0; rr < 2; rr++)
#pragma unroll
        for (int j = 0; j < 8; j++) {
            int col = col0 + tx * 8 + j;
            float v = acc[rr][j] + b_dt[col];
            float sp = (v > 20.f) ? v : log1pf(expf(v));
            float dt = sp * 0.099f + 0.001f;
            vals[rr][j] = dt;
            g_dt[(row0 + ty * 2 + rr) * DM + col] = dt;
        }
    __syncthreads();
    float (*ysm)[129] = (float (*)[129])(&Bsm[0][0]);
#pragma unroll
    for (int rr = 0; rr < 2; rr++)
#pragma unroll
        for (int j = 0; j < 8; j++)
            ysm[ty * 2 + rr][tx * 8 + j] = vals[rr][j];
    __syncthreads();
    {
        int b = row0 >> 11;
        int t0 = row0 & 2047;
        for (int i = tid; i < 32 * 128; i += 256) {
            int dcol = i >> 5, m = i & 31;
            g_dtT[((size_t)(b * 1024 + col0 + dcol)) * SSEQ + t0 + m] = ysm[m][dcol];
        }
    }
}

// ---------------- G & inp ----------------
__global__ __launch_bounds__(512) void ginp_kernel() {
    int r = blockIdx.x;
    int tid = threadIdx.x;
    int n = tid & 15, dg = tid >> 4;  // dg: 0..31
    const float* dtr = g_dt + r * DM;
    const float* ur  = g_xin + r * DM;
    float partial = 0.f;
#pragma unroll 8
    for (int i = 0; i < 32; i++) {
        int d = dg + (i << 5);
        float s = dtr[d] * ur[d];
        partial = fmaf(s, g_Aneg[d * 16 + n], partial);
    }
    __shared__ float red[32][16];
    red[dg][n] = partial;
    __syncthreads();
    for (int s2 = 16; s2 > 0; s2 >>= 1) {
        if (dg < s2) red[dg][n] += red[dg + s2][n];
        __syncthreads();
    }
    if (tid < 16) {
        float G = red[0][tid];
        g_inp [r * NS + tid] = g_proj[r * PP + 64 + tid] * G;
        g_Cbuf[r * NS + tid] = g_proj[r * PP + 80 + tid];
    }
}

// ---------------- scan (round-8 proven form) ----------------
__global__ __launch_bounds__(128) void scan_kernel(const float* __restrict__ Dp) {
    int lane = threadIdx.x & 15;
    int pair = blockIdx.x * 8 + (threadIdx.x >> 4);   // pair = b*1024 + d
    int b = pair >> 10, d = pair & 1023;
    float An  = g_Aneg[d * 16 + lane];
    float Dpd = Dp[d];
    const float* dtp  = g_dtT + (size_t)pair * SSEQ;
    const float* up   = g_uT  + (size_t)pair * SSEQ;
    const float* inpp = g_inp  + (size_t)b * SSEQ * NS;
    const float* Cp   = g_Cbuf + (size_t)b * SSEQ * NS;
    float* yp = g_yT + (size_t)pair * SSEQ;
    float h = 0.f;
#pragma unroll 4
    for (int t = 0; t < SSEQ; t++) {
        float dtv = __ldg(&dtp[t]);
        float uv  = __ldg(&up[t]);
        float e   = __expf(dtv * An);
        float iv  = __ldg(&inpp[t * NS + lane]);
        float cv  = __ldg(&Cp[t * NS + lane]);
        h = fmaf(e, h, iv);
        float p = h * cv;
        p += __shfl_xor_sync(0xffffffffu, p, 1);
        p += __shfl_xor_sync(0xffffffffu, p, 2);
        p += __shfl_xor_sync(0xffffffffu, p, 4);
        p += __shfl_xor_sync(0xffffffffu, p, 8);
        if (lane == 0) yp[t] = fmaf(Dpd, uv, p);
    }
}

// ---------------- output transpose: g_yT (1024x2048) -> out (2048x1024) -----
__global__ void transpose_out_kernel(float* __restrict__ outp) {
    const int rows = 1024, cols = 2048;
    __shared__ float tile[32][33];
    const float* s = g_yT + blockIdx.z * rows * cols;
    float* o = outp + blockIdx.z * rows * cols;
    int x = blockIdx.x * 32 + threadIdx.x;
    int y0 = blockIdx.y * 32;
#pragma unroll
    for (int j = threadIdx.y; j < 32; j += 8)
        tile[j][threadIdx.x] = s[(y0 + j) * cols + x];
    __syncthreads();
    int xr = y0 + threadIdx.x;
    int yc0 = blockIdx.x * 32;
#pragma unroll
    for (int j = threadIdx.y; j < 32; j += 8)
        o[(yc0 + j) * rows + xr] = tile[threadIdx.x][j];
}

// ---------------- launch (slot #3 = mma_gemm_kernel, profiled) ---------------
extern "C" void kernel_launch(void* const* d_in, const int* in_sizes, int n_in,
                              void* d_out, int out_size) {
    const float* x     = (const float*)d_in[0];
    const float* w_in  = (const float*)d_in[1];
    const float* w_x   = (const float*)d_in[2];
    const float* w_dt  = (const float*)d_in[3];
    const float* b_dt  = (const float*)d_in[4];
    const float* A_log = (const float*)d_in[5];
    const float* Dp    = (const float*)d_in[6];
    float* out = (float*)d_out;

    cudaFuncSetAttribute(mma_gemm_kernel,
                         cudaFuncAttributeMaxDynamicSharedMemorySize, 81920);
    cudaFuncSetAttribute(proj_mma_kernel,
                         cudaFuncAttributeMaxDynamicSharedMemorySize, 81920);

    convert_x_kernel<<<4096, 256>>>(x);                      // 0
    convert_w_kernel<<<dim3(32, 32), dim3(32, 8)>>>(w_in);   // 1
    convert_wx_kernel<<<dim3(32, 4), dim3(32, 8)>>>(w_x);    // 2
    mma_gemm_kernel<<<dim3(8, 32), 256, 81920>>>();          // 3 <- profiled
    proj_mma_kernel<<<dim3(4, 32), 256, 81920>>>();          // 4
    proj_reduce_kernel<<<512, 256>>>();                      // 5
    aneg_kernel<<<64, 256>>>(A_log);                         // 6
    dtproj_kernel<<<dim3(8, 128), 256>>>(w_dt, b_dt);        // 7
    ginp_kernel<<<4096, 512>>>();                            // 8
    scan_kernel<<<256, 128>>>(Dp);                           // 9
    transpose_out_kernel<<<dim3(64, 32, 2), dim3(32, 8)>>>(out); // 10
}